// round 2
// baseline (speedup 1.0000x reference)
#include <cuda_runtime.h>
#include <cuda_bf16.h>

// Problem constants
#define B_SZ   8192
#define D_SZ   8
#define P_SZ   10
#define R_SZ   512
#define OUT_SZ 64
#define NMID   6

// ---------------------------------------------------------------------------
// Device-global scratch (no allocations allowed in kernel_launch).
// ---------------------------------------------------------------------------
__device__ float g_tanh_g0[P_SZ * R_SZ];                    // tanh(G0)       [P,R]
__device__ float g_tanh_mid[NMID * R_SZ * P_SZ * R_SZ];     // tanh(G_mid)    [6,R,P,R]
__device__ float g_tanh_last[R_SZ * P_SZ * OUT_SZ];         // tanh(G_last)   [R,P,OUT]
__device__ float g_res0[B_SZ * R_SZ];
__device__ float g_res1[B_SZ * R_SZ];

// ---------------------------------------------------------------------------
// Elementwise tanh precompute
// ---------------------------------------------------------------------------
__global__ void tanh_kernel(const float* __restrict__ src, float* __restrict__ dst, int n) {
    int i = blockIdx.x * blockDim.x + threadIdx.x;
    int stride = gridDim.x * blockDim.x;
    for (; i < n; i += stride) dst[i] = tanhf(src[i]);
}

// ---------------------------------------------------------------------------
// First core: res0[b,r] = sum_j tanh(G0)[j,r] * z[b,0]^j
// ---------------------------------------------------------------------------
__global__ void first_core_kernel(const float* __restrict__ z, float* __restrict__ res) {
    int b = blockIdx.x;
    int r = threadIdx.x;                 // 512 threads
    float zv = z[b * D_SZ + 0];
    float ph = 1.f, acc = 0.f;
#pragma unroll
    for (int j = 0; j < P_SZ; j++) {
        acc += g_tanh_g0[j * R_SZ + r] * ph;
        ph *= zv;
    }
    res[b * R_SZ + r] = acc;
}

// ---------------------------------------------------------------------------
// Fused TT-contraction GEMM:
//   resout[b,k] = sum_{j<P} sum_{r<R} (z[b,zcol]^j * resin[b,r]) * G[r, j, k]
// A-tile (phi * res) is built on the fly in SMEM; G is the tanh'd core with
// row stride P*Nout (varying r) and column offset j*Nout.
// ---------------------------------------------------------------------------
template<int BM, int BN, int TM, int TN>
__global__ void __launch_bounds__((BM / TM) * (BN / TN))
tt_gemm_kernel(const float* __restrict__ resin,
               const float* __restrict__ G,
               const float* __restrict__ z, int zcol,
               float* __restrict__ resout, int Nout) {
    constexpr int BK = 32;
    constexpr int THREADS = (BM / TM) * (BN / TN);

    __shared__ float As[BM][BK];          // phi-scaled res tile (row-major)
    __shared__ float Bs[BK][BN];          // G tile
    __shared__ float phi_sm[BM];
    __shared__ float z_sm[BM];

    const int tid = threadIdx.x;
    const int rm0 = blockIdx.y * BM;
    const int cn0 = blockIdx.x * BN;
    const int tx  = tid % (BN / TN);
    const int ty  = tid / (BN / TN);

    for (int row = tid; row < BM; row += THREADS) {
        z_sm[row]   = z[(rm0 + row) * D_SZ + zcol];
        phi_sm[row] = 1.0f;
    }

    float acc[TM][TN];
#pragma unroll
    for (int i = 0; i < TM; i++)
#pragma unroll
        for (int j = 0; j < TN; j++) acc[i][j] = 0.f;

    for (int j = 0; j < P_SZ; j++) {
        if (j > 0) {
            // All phi reads of iteration j-1 completed before the trailing
            // __syncthreads() of the previous rc loop — safe to update.
            for (int row = tid; row < BM; row += THREADS) phi_sm[row] *= z_sm[row];
        }
        __syncthreads();

        for (int rc = 0; rc < R_SZ / BK; rc++) {
            // --- fill As: phi-scaled res chunk, float4 coalesced ---
#pragma unroll
            for (int it = 0; it < (BM * BK / 4) / THREADS; it++) {
                int idx = tid + it * THREADS;
                int row = idx / (BK / 4);
                int c4  = idx % (BK / 4);
                float4 v = *reinterpret_cast<const float4*>(
                    &resin[(size_t)(rm0 + row) * R_SZ + rc * BK + c4 * 4]);
                float ph = phi_sm[row];
                v.x *= ph; v.y *= ph; v.z *= ph; v.w *= ph;
                *reinterpret_cast<float4*>(&As[row][c4 * 4]) = v;
            }
            // --- fill Bs: G[r = rc*BK+kk, j, cn0+col] ---
#pragma unroll
            for (int it = 0; it < (BK * BN / 4) / THREADS; it++) {
                int idx = tid + it * THREADS;
                int kk  = idx / (BN / 4);
                int c4  = idx % (BN / 4);
                *reinterpret_cast<float4*>(&Bs[kk][c4 * 4]) =
                    *reinterpret_cast<const float4*>(
                        &G[(size_t)(rc * BK + kk) * (P_SZ * Nout)
                           + (size_t)j * Nout + cn0 + c4 * 4]);
            }
            __syncthreads();

#pragma unroll 8
            for (int kk = 0; kk < BK; kk++) {
                float a[TM], b[TN];
#pragma unroll
                for (int i = 0; i < TM; i++) a[i] = As[ty * TM + i][kk];
#pragma unroll
                for (int jj = 0; jj < TN; jj += 4) {
                    float4 bv = *reinterpret_cast<const float4*>(&Bs[kk][tx * TN + jj]);
                    b[jj + 0] = bv.x; b[jj + 1] = bv.y;
                    b[jj + 2] = bv.z; b[jj + 3] = bv.w;
                }
#pragma unroll
                for (int i = 0; i < TM; i++)
#pragma unroll
                    for (int jj = 0; jj < TN; jj++)
                        acc[i][jj] += a[i] * b[jj];
            }
            __syncthreads();
        }
    }

    // --- write out, float4 per 4 columns ---
#pragma unroll
    for (int i = 0; i < TM; i++) {
        int row = rm0 + ty * TM + i;
#pragma unroll
        for (int jj = 0; jj < TN; jj += 4) {
            float4 v = make_float4(acc[i][jj], acc[i][jj + 1], acc[i][jj + 2], acc[i][jj + 3]);
            *reinterpret_cast<float4*>(&resout[(size_t)row * Nout + cn0 + tx * TN + jj]) = v;
        }
    }
}

// ---------------------------------------------------------------------------
// Launch: graph-capturable, allocation-free, default stream only.
// Inputs (metadata order): z [B,D] f32, G0 [P,R] f32, G_mid [6,R,P,R] f32,
//                          G_last [R,P,OUT] f32, t (unused)
// Output: [B, OUT] f32
// ---------------------------------------------------------------------------
extern "C" void kernel_launch(void* const* d_in, const int* in_sizes, int n_in,
                              void* d_out, int out_size) {
    (void)in_sizes; (void)n_in; (void)out_size;
    const float* z      = (const float*)d_in[0];
    const float* G0     = (const float*)d_in[1];
    const float* Gmid   = (const float*)d_in[2];
    const float* Glast  = (const float*)d_in[3];
    float* out = (float*)d_out;

    float *p_tg0, *p_tmid, *p_tlast, *p_r0, *p_r1;
    cudaGetSymbolAddress((void**)&p_tg0,   g_tanh_g0);
    cudaGetSymbolAddress((void**)&p_tmid,  g_tanh_mid);
    cudaGetSymbolAddress((void**)&p_tlast, g_tanh_last);
    cudaGetSymbolAddress((void**)&p_r0,    g_res0);
    cudaGetSymbolAddress((void**)&p_r1,    g_res1);

    // 1) tanh precompute
    {
        int n0 = P_SZ * R_SZ;
        int nm = NMID * R_SZ * P_SZ * R_SZ;
        int nl = R_SZ * P_SZ * OUT_SZ;
        tanh_kernel<<<(n0 + 255) / 256, 256>>>(G0,    p_tg0,   n0);
        tanh_kernel<<<(nm + 255) / 256, 256>>>(Gmid,  p_tmid,  nm);
        tanh_kernel<<<(nl + 255) / 256, 256>>>(Glast, p_tlast, nl);
    }

    // 2) first core
    first_core_kernel<<<B_SZ, R_SZ>>>(z, p_r0);

    // 3) six middle cores, ping-pong
    float* cur = p_r0;
    float* nxt = p_r1;
    for (int i = 0; i < NMID; i++) {
        dim3 grid(R_SZ / 128, B_SZ / 128);
        tt_gemm_kernel<128, 128, 8, 8><<<grid, 256>>>(
            cur, p_tmid + (size_t)i * R_SZ * P_SZ * R_SZ, z, i + 1, nxt, R_SZ);
        float* t = cur; cur = nxt; nxt = t;
    }

    // 4) last core -> output [B, OUT]
    {
        dim3 grid(OUT_SZ / 64, B_SZ / 64);
        tt_gemm_kernel<64, 64, 4, 4><<<grid, 256>>>(
            cur, p_tlast, z, D_SZ - 1, out, OUT_SZ);
    }
}

// round 4
// speedup vs baseline: 2.9161x; 2.9161x over previous
#include <cuda_runtime.h>
#include <cuda_bf16.h>
#include <cstdint>
#include <cstddef>

// ---------------------------------------------------------------------------
// Problem constants
// ---------------------------------------------------------------------------
#define B_SZ   8192
#define D_SZ   8
#define P_SZ   10
#define R_SZ   512
#define OUT_SZ 64
#define NMID   6
#define KTOT   (P_SZ * R_SZ)   // 5120
#define KC     32              // K per chunk
#define NCH    (KTOT / KC)     // 160

// ---------------------------------------------------------------------------
// Device-global scratch
// ---------------------------------------------------------------------------
__device__ float g_tanh_g0[P_SZ * R_SZ];
__device__ float g_res0[B_SZ * R_SZ];
__device__ float g_res1[B_SZ * R_SZ];
// B operands: tanh'd, transposed to [n][k = j*512 + r], bf16 hi/lo split
__device__ __nv_bfloat16 g_bhi_mid[(size_t)NMID * R_SZ * KTOT];
__device__ __nv_bfloat16 g_blo_mid[(size_t)NMID * R_SZ * KTOT];
__device__ __nv_bfloat16 g_bhi_last[(size_t)OUT_SZ * KTOT];
__device__ __nv_bfloat16 g_blo_last[(size_t)OUT_SZ * KTOT];

// ---------------------------------------------------------------------------
// PTX helpers (sm_80-era only: cp.async, ldmatrix, mma.sync — no tcgen05)
// ---------------------------------------------------------------------------
__device__ __forceinline__ uint32_t smem_u32(const void* p) {
    uint32_t a;
    asm("{ .reg .u64 t; cvta.to.shared.u64 t, %1; cvt.u32.u64 %0, t; }" : "=r"(a) : "l"(p));
    return a;
}

#define CP_ASYNC16(dst, src) \
    asm volatile("cp.async.cg.shared.global [%0], [%1], 16;" :: "r"(dst), "l"(src) : "memory")
#define CP_COMMIT()  asm volatile("cp.async.commit_group;" ::: "memory")
#define CP_WAIT1()   asm volatile("cp.async.wait_group 1;" ::: "memory")
#define CP_WAIT0()   asm volatile("cp.async.wait_group 0;" ::: "memory")

#define LDSM4(r0, r1, r2, r3, addr) \
    asm volatile("ldmatrix.sync.aligned.m8n8.x4.shared.b16 {%0,%1,%2,%3}, [%4];" \
                 : "=r"(r0), "=r"(r1), "=r"(r2), "=r"(r3) : "r"(addr))

#define MMA_BF16(d, a, b) \
    asm volatile("mma.sync.aligned.m16n8k16.row.col.f32.bf16.bf16.f32 " \
                 "{%0,%1,%2,%3}, {%4,%5,%6,%7}, {%8,%9}, {%0,%1,%2,%3};" \
                 : "+f"((d)[0]), "+f"((d)[1]), "+f"((d)[2]), "+f"((d)[3]) \
                 : "r"((a)[0]), "r"((a)[1]), "r"((a)[2]), "r"((a)[3]), \
                   "r"((b)[0]), "r"((b)[1]))

// pack two f32 -> bf16x2 (lo = x0, hi = x1)
__device__ __forceinline__ uint32_t pack_bf16x2(float x0, float x1) {
    uint32_t r;
    asm("cvt.rn.bf16x2.f32 %0, %1, %2;" : "=r"(r) : "f"(x1), "f"(x0));
    return r;
}

// ---------------------------------------------------------------------------
// Precompute: tanh + tf->bf16 hi/lo split + transpose
//   G [R, P, N] (n contiguous)  ->  hi/lo [N][j*512 + r]  (k contiguous)
// ---------------------------------------------------------------------------
__global__ void split_transpose_kernel(const float* __restrict__ G,
                                       __nv_bfloat16* __restrict__ hi,
                                       __nv_bfloat16* __restrict__ lo, int N) {
    __shared__ float t[32][33];
    int j  = blockIdx.z;
    int rt = blockIdx.x * 32, nt = blockIdx.y * 32;
    int tx = threadIdx.x, ty = threadIdx.y;   // block (32, 8)
#pragma unroll
    for (int yy = ty; yy < 32; yy += 8)
        t[yy][tx] = tanhf(G[((size_t)(rt + yy) * P_SZ + j) * N + nt + tx]);
    __syncthreads();
#pragma unroll
    for (int yy = ty; yy < 32; yy += 8) {
        int n = nt + yy, r = rt + tx;
        float x = t[tx][yy];
        __nv_bfloat16 h = __float2bfloat16_rn(x);
        float l = x - __bfloat162float(h);
        size_t o = (size_t)n * KTOT + (size_t)j * R_SZ + r;
        hi[o] = h;
        lo[o] = __float2bfloat16_rn(l);
    }
}

__global__ void tanh_kernel(const float* __restrict__ src, float* __restrict__ dst, int n) {
    int i = blockIdx.x * blockDim.x + threadIdx.x;
    if (i < n) dst[i] = tanhf(src[i]);
}

// First core: res0[b,r] = sum_j tanh(G0)[j,r] * z[b,0]^j
__global__ void first_core_kernel(const float* __restrict__ z, float* __restrict__ res) {
    int b = blockIdx.x;
    int r = threadIdx.x;
    float zv = z[b * D_SZ + 0];
    float ph = 1.f, acc = 0.f;
#pragma unroll
    for (int j = 0; j < P_SZ; j++) {
        acc += g_tanh_g0[j * R_SZ + r] * ph;
        ph *= zv;
    }
    res[b * R_SZ + r] = acc;
}

// ---------------------------------------------------------------------------
// HMMA bf16 3-pass-split GEMM with on-the-fly A = phi * res construction.
//   out[m,n] = sum_K A[m,K] B[n,K],  K = j*512+r,  A = z[m]^j * res[m,r]
// 8 warps in (BM/WM) x (BN/WN) layout; cp.async double buffer for B,
// STS-built double buffer for A (hi/lo each).
// ---------------------------------------------------------------------------
template<int BM, int BN, int WM, int WN>
__global__ void __launch_bounds__(256, 2)
tt_mma_kernel(const float* __restrict__ resin,
              const __nv_bfloat16* __restrict__ Bhi,
              const __nv_bfloat16* __restrict__ Blo,
              const float* __restrict__ z, int zcol,
              float* __restrict__ outp, int Ntotal) {
    constexpr int AST = 80;                 // bytes/row: 32 bf16 (64B) + 16B pad
    constexpr int BST = 80;
    constexpr int A_TILE = BM * AST;
    constexpr int B_TILE = BN * BST;
    constexpr int MT = WM / 16, NT = WN / 8;
    constexpr int AROWS = BM / 32;          // float4 row-groups per thread

    extern __shared__ __align__(16) char sm[];
    const uint32_t base = smem_u32(sm);
    // layout: A[stage][hi/lo], then B[stage][hi/lo]
    const uint32_t aA = base;
    const uint32_t bA = base + 4 * A_TILE;

    const int tid = threadIdx.x, lane = tid & 31, wid = tid >> 5;
    const int m0 = blockIdx.y * BM, n0 = blockIdx.x * BN;
    constexpr int NWC = BN / WN;
    const int wm0 = (wid / NWC) * WM;
    const int wn0 = (wid % NWC) * WN;

    // producer mapping for A: thread -> (rows ar0+32i, 4 cols at ac4*4)
    const int ar0 = tid >> 3;
    const int ac4 = tid & 7;

    float zr[AROWS], ph[AROWS];
#pragma unroll
    for (int i = 0; i < AROWS; i++) {
        zr[i] = z[(size_t)(m0 + ar0 + 32 * i) * D_SZ + zcol];
        ph[i] = 1.0f;
    }
    int jcur = 0;

    float acc[MT][NT][4];
#pragma unroll
    for (int mt = 0; mt < MT; mt++)
#pragma unroll
        for (int nt = 0; nt < NT; nt++)
#pragma unroll
            for (int q = 0; q < 4; q++) acc[mt][nt][q] = 0.f;

    auto produce = [&](int cc) {
        const int s = cc & 1;
        const int j = cc >> 4;
        if (j != jcur) {
#pragma unroll
            for (int i = 0; i < AROWS; i++) ph[i] *= zr[i];
            jcur = j;
        }
        const int roff = (cc & 15) * KC;
        const uint32_t aH = aA + (2 * s + 0) * A_TILE;
        const uint32_t aL = aA + (2 * s + 1) * A_TILE;
#pragma unroll
        for (int i = 0; i < AROWS; i++) {
            const int row = ar0 + 32 * i;
            float4 v = *reinterpret_cast<const float4*>(
                &resin[(size_t)(m0 + row) * R_SZ + roff + ac4 * 4]);
            const float p = ph[i];
            float x0 = v.x * p, x1 = v.y * p, x2 = v.z * p, x3 = v.w * p;
            float h0 = __bfloat162float(__float2bfloat16_rn(x0));
            float h1 = __bfloat162float(__float2bfloat16_rn(x1));
            float h2 = __bfloat162float(__float2bfloat16_rn(x2));
            float h3 = __bfloat162float(__float2bfloat16_rn(x3));
            uint32_t hp0 = pack_bf16x2(h0, h1), hp1 = pack_bf16x2(h2, h3);
            uint32_t lp0 = pack_bf16x2(x0 - h0, x1 - h1);
            uint32_t lp1 = pack_bf16x2(x2 - h2, x3 - h3);
            const uint32_t off = (uint32_t)(row * AST + ac4 * 8);
            asm volatile("st.shared.v2.b32 [%0], {%1, %2};"
                         :: "r"(aH + off), "r"(hp0), "r"(hp1) : "memory");
            asm volatile("st.shared.v2.b32 [%0], {%1, %2};"
                         :: "r"(aL + off), "r"(lp0), "r"(lp1) : "memory");
        }
        const uint32_t bH = bA + (2 * s + 0) * B_TILE;
        const uint32_t bL = bA + (2 * s + 1) * B_TILE;
#pragma unroll
        for (int i = 0; i < (BN * 4) / 256; i++) {
            const int idx = tid + 256 * i;
            const int n = idx >> 2, c16 = idx & 3;
            const size_t go = (size_t)(n0 + n) * KTOT + (size_t)cc * KC + c16 * 8;
            const uint32_t off = (uint32_t)(n * BST + c16 * 16);
            CP_ASYNC16(bH + off, Bhi + go);
            CP_ASYNC16(bL + off, Blo + go);
        }
        CP_COMMIT();
    };

    // per-lane ldmatrix address components
    const uint32_t a_lane = (uint32_t)((wm0 + (lane & 15)) * AST + (lane >> 4) * 16);
    const uint32_t b_lane = (uint32_t)((wn0 + ((lane >> 4) << 3) + (lane & 7)) * BST
                                       + ((lane >> 3) & 1) * 16);

    auto mma_chunk = [&](int s) {
        const uint32_t aH = aA + (2 * s + 0) * A_TILE;
        const uint32_t aL = aA + (2 * s + 1) * A_TILE;
        const uint32_t bH = bA + (2 * s + 0) * B_TILE;
        const uint32_t bL = bA + (2 * s + 1) * B_TILE;
#pragma unroll
        for (int ks = 0; ks < 2; ks++) {
            uint32_t bh[NT][2], bl[NT][2];
#pragma unroll
            for (int n2 = 0; n2 < NT / 2; n2++) {
                LDSM4(bh[2 * n2][0], bh[2 * n2][1], bh[2 * n2 + 1][0], bh[2 * n2 + 1][1],
                      bH + b_lane + n2 * 16 * BST + ks * 32);
                LDSM4(bl[2 * n2][0], bl[2 * n2][1], bl[2 * n2 + 1][0], bl[2 * n2 + 1][1],
                      bL + b_lane + n2 * 16 * BST + ks * 32);
            }
            uint32_t a[MT][4];
#pragma unroll
            for (int mt = 0; mt < MT; mt++)
                LDSM4(a[mt][0], a[mt][1], a[mt][2], a[mt][3],
                      aH + a_lane + mt * 16 * AST + ks * 32);
#pragma unroll
            for (int mt = 0; mt < MT; mt++)
#pragma unroll
                for (int nt = 0; nt < NT; nt++) MMA_BF16(acc[mt][nt], a[mt], bh[nt]);
#pragma unroll
            for (int mt = 0; mt < MT; mt++)
#pragma unroll
                for (int nt = 0; nt < NT; nt++) MMA_BF16(acc[mt][nt], a[mt], bl[nt]);
#pragma unroll
            for (int mt = 0; mt < MT; mt++)
                LDSM4(a[mt][0], a[mt][1], a[mt][2], a[mt][3],
                      aL + a_lane + mt * 16 * AST + ks * 32);
#pragma unroll
            for (int mt = 0; mt < MT; mt++)
#pragma unroll
                for (int nt = 0; nt < NT; nt++) MMA_BF16(acc[mt][nt], a[mt], bh[nt]);
        }
    };

    produce(0);
    for (int c = 0; c < NCH; c++) {
        if (c + 1 < NCH) { produce(c + 1); CP_WAIT1(); }
        else             { CP_WAIT0(); }
        __syncthreads();
        mma_chunk(c & 1);
        __syncthreads();
    }

    // epilogue: f32 accum -> global
#pragma unroll
    for (int mt = 0; mt < MT; mt++) {
        const int row0 = m0 + wm0 + mt * 16 + (lane >> 2);
#pragma unroll
        for (int nt = 0; nt < NT; nt++) {
            const int col = n0 + wn0 + nt * 8 + (lane & 3) * 2;
            *reinterpret_cast<float2*>(&outp[(size_t)row0 * Ntotal + col]) =
                make_float2(acc[mt][nt][0], acc[mt][nt][1]);
            *reinterpret_cast<float2*>(&outp[(size_t)(row0 + 8) * Ntotal + col]) =
                make_float2(acc[mt][nt][2], acc[mt][nt][3]);
        }
    }
}

// ---------------------------------------------------------------------------
// Launch (graph-capturable, allocation-free)
// Inputs: z [B,D] f32, G0 [P,R] f32, G_mid [6,R,P,R] f32, G_last [R,P,OUT] f32, t
// Output: [B, OUT] f32
// ---------------------------------------------------------------------------
extern "C" void kernel_launch(void* const* d_in, const int* in_sizes, int n_in,
                              void* d_out, int out_size) {
    (void)in_sizes; (void)n_in; (void)out_size;
    const float* z     = (const float*)d_in[0];
    const float* G0    = (const float*)d_in[1];
    const float* Gmid  = (const float*)d_in[2];
    const float* Glast = (const float*)d_in[3];
    float* out = (float*)d_out;

    float *p_tg0, *p_r0, *p_r1;
    __nv_bfloat16 *p_bhi, *p_blo, *p_bhiL, *p_bloL;
    cudaGetSymbolAddress((void**)&p_tg0,  g_tanh_g0);
    cudaGetSymbolAddress((void**)&p_r0,   g_res0);
    cudaGetSymbolAddress((void**)&p_r1,   g_res1);
    cudaGetSymbolAddress((void**)&p_bhi,  g_bhi_mid);
    cudaGetSymbolAddress((void**)&p_blo,  g_blo_mid);
    cudaGetSymbolAddress((void**)&p_bhiL, g_bhi_last);
    cudaGetSymbolAddress((void**)&p_bloL, g_blo_last);

    // smem: 4 A tiles + 4 B tiles, 80B row stride
    const int SMEM_MID  = 4 * 128 * 80 + 4 * 128 * 80;  // 81920
    const int SMEM_LAST = 4 * 64 * 80 + 4 * 64 * 80;    // 40960
    cudaFuncSetAttribute((const void*)tt_mma_kernel<128, 128, 64, 32>,
                         cudaFuncAttributeMaxDynamicSharedMemorySize, SMEM_MID);
    cudaFuncSetAttribute((const void*)tt_mma_kernel<64, 64, 32, 16>,
                         cudaFuncAttributeMaxDynamicSharedMemorySize, SMEM_LAST);

    // 1) precompute: tanh(G0); tanh+split+transpose all B operands
    tanh_kernel<<<(P_SZ * R_SZ + 255) / 256, 256>>>(G0, p_tg0, P_SZ * R_SZ);
    for (int i = 0; i < NMID; i++) {
        split_transpose_kernel<<<dim3(R_SZ / 32, R_SZ / 32, P_SZ), dim3(32, 8)>>>(
            Gmid + (size_t)i * R_SZ * P_SZ * R_SZ,
            p_bhi + (size_t)i * R_SZ * KTOT,
            p_blo + (size_t)i * R_SZ * KTOT, R_SZ);
    }
    split_transpose_kernel<<<dim3(R_SZ / 32, OUT_SZ / 32, P_SZ), dim3(32, 8)>>>(
        Glast, p_bhiL, p_bloL, OUT_SZ);

    // 2) first core
    first_core_kernel<<<B_SZ, R_SZ>>>(z, p_r0);

    // 3) six middle cores on the tensor pipe (ping-pong)
    float* cur = p_r0;
    float* nxt = p_r1;
    for (int i = 0; i < NMID; i++) {
        tt_mma_kernel<128, 128, 64, 32><<<dim3(R_SZ / 128, B_SZ / 128), 256, SMEM_MID>>>(
            cur, p_bhi + (size_t)i * R_SZ * KTOT, p_blo + (size_t)i * R_SZ * KTOT,
            z, i + 1, nxt, R_SZ);
        float* t = cur; cur = nxt; nxt = t;
    }

    // 4) last core -> d_out [B, OUT]
    tt_mma_kernel<64, 64, 32, 16><<<dim3(OUT_SZ / 64, B_SZ / 64), 256, SMEM_LAST>>>(
        cur, p_bhiL, p_bloL, z, D_SZ - 1, out, OUT_SZ);
}

// round 5
// speedup vs baseline: 3.3655x; 1.1541x over previous
#include <cuda_runtime.h>
#include <cuda_bf16.h>
#include <cstdint>
#include <cstddef>

// ---------------------------------------------------------------------------
// Problem constants
// ---------------------------------------------------------------------------
#define B_SZ   8192
#define D_SZ   8
#define P_SZ   10
#define R_SZ   512
#define OUT_SZ 64
#define NMID   6
#define KTOT   (P_SZ * R_SZ)   // 5120
#define KC     32              // K per pipeline chunk
#define RCH    (R_SZ / KC)     // 16 chunks per j
#define NCH    (KTOT / KC)     // 160

// ---------------------------------------------------------------------------
// Device-global scratch
// ---------------------------------------------------------------------------
__device__ float g_tanh_g0[P_SZ * R_SZ];
// res ping-pong, stored pre-split as bf16 hi/lo
__device__ __nv_bfloat16 g_rh0[(size_t)B_SZ * R_SZ];
__device__ __nv_bfloat16 g_rl0[(size_t)B_SZ * R_SZ];
__device__ __nv_bfloat16 g_rh1[(size_t)B_SZ * R_SZ];
__device__ __nv_bfloat16 g_rl1[(size_t)B_SZ * R_SZ];
// B operands: tanh'd, transposed to [n][k = j*512 + r], bf16 hi/lo split
__device__ __nv_bfloat16 g_bhi_mid[(size_t)NMID * R_SZ * KTOT];
__device__ __nv_bfloat16 g_blo_mid[(size_t)NMID * R_SZ * KTOT];
__device__ __nv_bfloat16 g_bhi_last[(size_t)OUT_SZ * KTOT];
__device__ __nv_bfloat16 g_blo_last[(size_t)OUT_SZ * KTOT];

// ---------------------------------------------------------------------------
// PTX helpers (sm_80-era: cp.async, ldmatrix, mma.sync — NO tcgen05)
// ---------------------------------------------------------------------------
__device__ __forceinline__ uint32_t smem_u32(const void* p) {
    uint32_t a;
    asm("{ .reg .u64 t; cvta.to.shared.u64 t, %1; cvt.u32.u64 %0, t; }" : "=r"(a) : "l"(p));
    return a;
}
#define CP_ASYNC16(dst, src) \
    asm volatile("cp.async.cg.shared.global [%0], [%1], 16;" :: "r"(dst), "l"(src) : "memory")
#define CP_COMMIT() asm volatile("cp.async.commit_group;" ::: "memory")
#define CP_WAIT2()  asm volatile("cp.async.wait_group 2;" ::: "memory")

#define LDSM4(r0, r1, r2, r3, addr) \
    asm volatile("ldmatrix.sync.aligned.m8n8.x4.shared.b16 {%0,%1,%2,%3}, [%4];" \
                 : "=r"(r0), "=r"(r1), "=r"(r2), "=r"(r3) : "r"(addr))

#define MMA_BF16(d, a, b) \
    asm volatile("mma.sync.aligned.m16n8k16.row.col.f32.bf16.bf16.f32 " \
                 "{%0,%1,%2,%3}, {%4,%5,%6,%7}, {%8,%9}, {%0,%1,%2,%3};" \
                 : "+f"((d)[0]), "+f"((d)[1]), "+f"((d)[2]), "+f"((d)[3]) \
                 : "r"((a)[0]), "r"((a)[1]), "r"((a)[2]), "r"((a)[3]), \
                   "r"((b)[0]), "r"((b)[1]))

// 64B-row XOR swizzle: conflict-free across all 8-row ldmatrix phases.
// c16 slot XORed with (row>>1)&3 so rows {r, r+2, r+4, r+6} hit distinct slots.
__device__ __forceinline__ uint32_t sw64(uint32_t row, uint32_t c16) {
    return row * 64u + ((c16 ^ ((row >> 1) & 3u)) << 4);
}

// ---------------------------------------------------------------------------
// Precompute: tanh + bf16 hi/lo split + transpose
//   G [R, P, N] (n contiguous) -> hi/lo [N][j*512 + r] (k contiguous)
// blockIdx.z enumerates (layer, j); layer offsets via strides.
// ---------------------------------------------------------------------------
__global__ void split_transpose_kernel(const float* __restrict__ G,
                                       __nv_bfloat16* __restrict__ hi,
                                       __nv_bfloat16* __restrict__ lo,
                                       int N, size_t gStride, size_t oStride) {
    __shared__ float t[32][33];
    int layer = blockIdx.z / P_SZ;
    int j     = blockIdx.z % P_SZ;
    const float* Gp = G + (size_t)layer * gStride;
    __nv_bfloat16* hip = hi + (size_t)layer * oStride;
    __nv_bfloat16* lop = lo + (size_t)layer * oStride;
    int rt = blockIdx.x * 32, nt = blockIdx.y * 32;
    int tx = threadIdx.x, ty = threadIdx.y;   // block (32, 8)
#pragma unroll
    for (int yy = ty; yy < 32; yy += 8)
        t[yy][tx] = tanhf(Gp[((size_t)(rt + yy) * P_SZ + j) * N + nt + tx]);
    __syncthreads();
#pragma unroll
    for (int yy = ty; yy < 32; yy += 8) {
        int n = nt + yy, r = rt + tx;
        float x = t[tx][yy];
        __nv_bfloat16 h = __float2bfloat16_rn(x);
        size_t o = (size_t)n * KTOT + (size_t)j * R_SZ + r;
        hip[o] = h;
        lop[o] = __float2bfloat16_rn(x - __bfloat162float(h));
    }
}

// First core: res0[b,r] = sum_j tanh(G0)[j,r] * z[b,0]^j, written as hi/lo split
__global__ void first_core_kernel(const float* __restrict__ z,
                                  __nv_bfloat16* __restrict__ rh,
                                  __nv_bfloat16* __restrict__ rl) {
    int b = blockIdx.x;
    int r = threadIdx.x;
    float zv = z[b * D_SZ + 0];
    float ph = 1.f, acc = 0.f;
#pragma unroll
    for (int j = 0; j < P_SZ; j++) {
        acc += g_tanh_g0[j * R_SZ + r] * ph;
        ph *= zv;
    }
    __nv_bfloat16 h = __float2bfloat16_rn(acc);
    rh[(size_t)b * R_SZ + r] = h;
    rl[(size_t)b * R_SZ + r] = __float2bfloat16_rn(acc - __bfloat162float(h));
}

// ---------------------------------------------------------------------------
// HMMA bf16 3-product-split GEMM with Horner phi folding:
//   out[m,n] = sum_{j desc} ( acc *= z_m ; acc += sum_r res[m,r] G_j[r,n] )
// Both operands streamed via cp.async (4-stage); A = pre-split res.
// EPI 0: write bf16 hi/lo split (feeds next layer). EPI 1: write f32.
// ---------------------------------------------------------------------------
template<int BM, int BN, int WM, int WN, int EPI>
__global__ void __launch_bounds__(256, 1)
tt_mma_kernel(const __nv_bfloat16* __restrict__ Ahi,
              const __nv_bfloat16* __restrict__ Alo,
              const __nv_bfloat16* __restrict__ Bhi,
              const __nv_bfloat16* __restrict__ Blo,
              const float* __restrict__ z, int zcol,
              float* __restrict__ outF,
              __nv_bfloat16* __restrict__ outH,
              __nv_bfloat16* __restrict__ outL, int Ntotal) {
    constexpr int MT = WM / 16, NT = WN / 8;
    constexpr int A_T = BM * 64;               // one A tile (hi or lo), bytes
    constexpr int B_T = BN * 64;
    constexpr int STAGE = 2 * A_T + 2 * B_T;
    constexpr int NSTAGE = 4;

    extern __shared__ __align__(16) char sm[];
    const uint32_t base = smem_u32(sm);

    const int tid = threadIdx.x, lane = tid & 31, wid = tid >> 5;
    const int m0 = blockIdx.y * BM, n0 = blockIdx.x * BN;
    constexpr int NWC = BN / WN;
    const int wm0 = (wid / NWC) * WM;
    const int wn0 = (wid % NWC) * WN;

    // per-lane z values for Horner scaling (2 rows per mt quad)
    float zA[MT], zB[MT];
#pragma unroll
    for (int mt = 0; mt < MT; mt++) {
        int rA = m0 + wm0 + mt * 16 + (lane >> 2);
        zA[mt] = z[(size_t)rA * D_SZ + zcol];
        zB[mt] = z[(size_t)(rA + 8) * D_SZ + zcol];
    }

    float acc[MT][NT][4];
#pragma unroll
    for (int mt = 0; mt < MT; mt++)
#pragma unroll
        for (int nt = 0; nt < NT; nt++)
#pragma unroll
            for (int q = 0; q < 4; q++) acc[mt][nt][q] = 0.f;

    auto produce = [&](int cc) {
        const int s = cc & (NSTAGE - 1);
        const int j = (P_SZ - 1) - cc / RCH;       // descending j
        const int rr = cc & (RCH - 1);
        const int roffA = rr * KC;
        const int koffB = j * R_SZ + rr * KC;
        const uint32_t aH = base + s * STAGE;
        const uint32_t aL = aH + A_T;
        const uint32_t bH = aH + 2 * A_T;
        const uint32_t bL = bH + B_T;
#pragma unroll
        for (int i = 0; i < (BM * 4) / 256; i++) {
            const int idx = tid + i * 256;
            const int row = idx >> 2, c16 = idx & 3;
            const uint32_t off = sw64(row, c16);
            const size_t go = (size_t)(m0 + row) * R_SZ + roffA + c16 * 8;
            CP_ASYNC16(aH + off, Ahi + go);
            CP_ASYNC16(aL + off, Alo + go);
        }
#pragma unroll
        for (int i = 0; i < (BN * 4) / 256; i++) {
            const int idx = tid + i * 256;
            const int row = idx >> 2, c16 = idx & 3;
            const uint32_t off = sw64(row, c16);
            const size_t go = (size_t)(n0 + row) * KTOT + koffB + c16 * 8;
            CP_ASYNC16(bH + off, Bhi + go);
            CP_ASYNC16(bL + off, Blo + go);
        }
        CP_COMMIT();
    };

    auto mma_chunk = [&](int s) {
        const uint32_t aH = base + s * STAGE;
        const uint32_t aL = aH + A_T;
        const uint32_t bH = aH + 2 * A_T;
        const uint32_t bL = bH + B_T;
#pragma unroll
        for (int ks = 0; ks < 2; ks++) {
            uint32_t bh[NT][2], bl[NT][2];
#pragma unroll
            for (int n2 = 0; n2 < NT / 2; n2++) {
                const uint32_t rowb = wn0 + n2 * 16 + ((lane >> 4) << 3) + (lane & 7);
                const uint32_t c16b = ((lane >> 3) & 1) + 2 * ks;
                LDSM4(bh[2 * n2][0], bh[2 * n2][1], bh[2 * n2 + 1][0], bh[2 * n2 + 1][1],
                      bH + sw64(rowb, c16b));
                LDSM4(bl[2 * n2][0], bl[2 * n2][1], bl[2 * n2 + 1][0], bl[2 * n2 + 1][1],
                      bL + sw64(rowb, c16b));
            }
            uint32_t a[MT][4];
#pragma unroll
            for (int mt = 0; mt < MT; mt++) {
                const uint32_t rowa = wm0 + mt * 16 + (lane & 15);
                LDSM4(a[mt][0], a[mt][1], a[mt][2], a[mt][3],
                      aH + sw64(rowa, (lane >> 4) + 2 * ks));
            }
#pragma unroll
            for (int mt = 0; mt < MT; mt++)
#pragma unroll
                for (int nt = 0; nt < NT; nt++) MMA_BF16(acc[mt][nt], a[mt], bh[nt]);
#pragma unroll
            for (int mt = 0; mt < MT; mt++)
#pragma unroll
                for (int nt = 0; nt < NT; nt++) MMA_BF16(acc[mt][nt], a[mt], bl[nt]);
#pragma unroll
            for (int mt = 0; mt < MT; mt++) {
                const uint32_t rowa = wm0 + mt * 16 + (lane & 15);
                LDSM4(a[mt][0], a[mt][1], a[mt][2], a[mt][3],
                      aL + sw64(rowa, (lane >> 4) + 2 * ks));
            }
#pragma unroll
            for (int mt = 0; mt < MT; mt++)
#pragma unroll
                for (int nt = 0; nt < NT; nt++) MMA_BF16(acc[mt][nt], a[mt], bh[nt]);
        }
    };

    // prologue: 3 stages in flight
    produce(0); produce(1); produce(2);

    for (int c = 0; c < NCH; c++) {
        CP_WAIT2();
        __syncthreads();
        if (c + 3 < NCH) produce(c + 3); else CP_COMMIT();
        if (c && (c & (RCH - 1)) == 0) {
            // Horner: entering next-lower j — scale accumulators by z
#pragma unroll
            for (int mt = 0; mt < MT; mt++)
#pragma unroll
                for (int nt = 0; nt < NT; nt++) {
                    acc[mt][nt][0] *= zA[mt]; acc[mt][nt][1] *= zA[mt];
                    acc[mt][nt][2] *= zB[mt]; acc[mt][nt][3] *= zB[mt];
                }
        }
        mma_chunk(c & (NSTAGE - 1));
    }

    // epilogue
#pragma unroll
    for (int mt = 0; mt < MT; mt++) {
        const int row0 = m0 + wm0 + mt * 16 + (lane >> 2);
#pragma unroll
        for (int nt = 0; nt < NT; nt++) {
            const int col = n0 + wn0 + nt * 8 + (lane & 3) * 2;
            if (EPI == 1) {
                *reinterpret_cast<float2*>(&outF[(size_t)row0 * Ntotal + col]) =
                    make_float2(acc[mt][nt][0], acc[mt][nt][1]);
                *reinterpret_cast<float2*>(&outF[(size_t)(row0 + 8) * Ntotal + col]) =
                    make_float2(acc[mt][nt][2], acc[mt][nt][3]);
            } else {
#pragma unroll
                for (int h = 0; h < 2; h++) {
                    const int row = row0 + 8 * h;
                    float v0 = acc[mt][nt][2 * h], v1 = acc[mt][nt][2 * h + 1];
                    __nv_bfloat16 h0 = __float2bfloat16_rn(v0);
                    __nv_bfloat16 h1 = __float2bfloat16_rn(v1);
                    __nv_bfloat162 hv; hv.x = h0; hv.y = h1;
                    __nv_bfloat162 lv;
                    lv.x = __float2bfloat16_rn(v0 - __bfloat162float(h0));
                    lv.y = __float2bfloat16_rn(v1 - __bfloat162float(h1));
                    *reinterpret_cast<__nv_bfloat162*>(&outH[(size_t)row * R_SZ + col]) = hv;
                    *reinterpret_cast<__nv_bfloat162*>(&outL[(size_t)row * R_SZ + col]) = lv;
                }
            }
        }
    }
}

// ---------------------------------------------------------------------------
// Launch (graph-capturable, allocation-free)
// Inputs: z [B,D] f32, G0 [P,R] f32, G_mid [6,R,P,R] f32, G_last [R,P,OUT] f32, t
// Output: [B, OUT] f32
// ---------------------------------------------------------------------------
extern "C" void kernel_launch(void* const* d_in, const int* in_sizes, int n_in,
                              void* d_out, int out_size) {
    (void)in_sizes; (void)n_in; (void)out_size;
    const float* z     = (const float*)d_in[0];
    const float* G0    = (const float*)d_in[1];
    const float* Gmid  = (const float*)d_in[2];
    const float* Glast = (const float*)d_in[3];
    float* out = (float*)d_out;

    float* p_tg0;
    __nv_bfloat16 *p_rh0, *p_rl0, *p_rh1, *p_rl1, *p_bhi, *p_blo, *p_bhiL, *p_bloL;
    cudaGetSymbolAddress((void**)&p_tg0,  g_tanh_g0);
    cudaGetSymbolAddress((void**)&p_rh0,  g_rh0);
    cudaGetSymbolAddress((void**)&p_rl0,  g_rl0);
    cudaGetSymbolAddress((void**)&p_rh1,  g_rh1);
    cudaGetSymbolAddress((void**)&p_rl1,  g_rl1);
    cudaGetSymbolAddress((void**)&p_bhi,  g_bhi_mid);
    cudaGetSymbolAddress((void**)&p_blo,  g_blo_mid);
    cudaGetSymbolAddress((void**)&p_bhiL, g_bhi_last);
    cudaGetSymbolAddress((void**)&p_bloL, g_blo_last);

    // dynamic smem: 4 stages x (2*BM + 2*BN) * 64 bytes
    const int SMEM_MID  = 4 * (2 * 256 + 2 * 128) * 64;  // 196608
    const int SMEM_LAST = 4 * (2 * 64 + 2 * 64) * 64;    // 65536
    cudaFuncSetAttribute((const void*)tt_mma_kernel<256, 128, 64, 64, 0>,
                         cudaFuncAttributeMaxDynamicSharedMemorySize, SMEM_MID);
    cudaFuncSetAttribute((const void*)tt_mma_kernel<64, 64, 32, 16, 1>,
                         cudaFuncAttributeMaxDynamicSharedMemorySize, SMEM_LAST);

    // tanh(G0)
    {
        int n0 = P_SZ * R_SZ;
        // reuse split_transpose? G0 is tiny; simple elementwise via first-core path:
        // do it with a tiny lambda-kernel-free approach: one split_transpose won't fit.
        // dedicated mini kernel:
        extern __global__ void tanh_small_kernel(const float*, float*, int);
        tanh_small_kernel<<<(n0 + 255) / 256, 256>>>(G0, p_tg0, n0);
    }

    // B precompute: all 6 mid layers in ONE launch; last separate
    split_transpose_kernel<<<dim3(R_SZ / 32, R_SZ / 32, NMID * P_SZ), dim3(32, 8)>>>(
        Gmid, p_bhi, p_blo, R_SZ,
        (size_t)R_SZ * P_SZ * R_SZ, (size_t)R_SZ * KTOT);
    split_transpose_kernel<<<dim3(R_SZ / 32, OUT_SZ / 32, P_SZ), dim3(32, 8)>>>(
        Glast, p_bhiL, p_bloL, OUT_SZ, 0, 0);

    // first core -> split res0
    first_core_kernel<<<B_SZ, R_SZ>>>(z, p_rh0, p_rl0);

    // six middle cores (ping-pong on split res)
    __nv_bfloat16 *ch = p_rh0, *cl = p_rl0, *nh = p_rh1, *nl = p_rl1;
    for (int i = 0; i < NMID; i++) {
        tt_mma_kernel<256, 128, 64, 64, 0><<<dim3(R_SZ / 128, B_SZ / 256), 256, SMEM_MID>>>(
            ch, cl,
            p_bhi + (size_t)i * R_SZ * KTOT, p_blo + (size_t)i * R_SZ * KTOT,
            z, i + 1, nullptr, nh, nl, R_SZ);
        __nv_bfloat16* t;
        t = ch; ch = nh; nh = t;
        t = cl; cl = nl; nl = t;
    }

    // last core -> d_out [B, OUT] f32
    tt_mma_kernel<64, 64, 32, 16, 1><<<dim3(1, B_SZ / 64), 256, SMEM_LAST>>>(
        ch, cl, p_bhiL, p_bloL, z, D_SZ - 1, out, nullptr, nullptr, OUT_SZ);
}

// small tanh kernel (defined after use; declared above)
__global__ void tanh_small_kernel(const float* __restrict__ src,
                                  float* __restrict__ dst, int n) {
    int i = blockIdx.x * blockDim.x + threadIdx.x;
    if (i < n) dst[i] = tanhf(src[i]);
}

// round 6
// speedup vs baseline: 3.4446x; 1.0235x over previous
#include <cuda_runtime.h>
#include <cuda_bf16.h>
#include <cstdint>
#include <cstddef>

// ---------------------------------------------------------------------------
// Problem constants
// ---------------------------------------------------------------------------
#define B_SZ   8192
#define D_SZ   8
#define P_SZ   10
#define R_SZ   512
#define OUT_SZ 64
#define NMID   6
#define KTOT   (P_SZ * R_SZ)   // 5120
#define KC     32              // K per pipeline chunk
#define RCH    (R_SZ / KC)     // 16 chunks per j
#define NCH    (KTOT / KC)     // 160

// ---------------------------------------------------------------------------
// Device-global scratch
// ---------------------------------------------------------------------------
__device__ float g_tanh_g0[P_SZ * R_SZ];
__device__ __nv_bfloat16 g_rh0[(size_t)B_SZ * R_SZ];
__device__ __nv_bfloat16 g_rl0[(size_t)B_SZ * R_SZ];
__device__ __nv_bfloat16 g_rh1[(size_t)B_SZ * R_SZ];
__device__ __nv_bfloat16 g_rl1[(size_t)B_SZ * R_SZ];
__device__ __nv_bfloat16 g_bhi_mid[(size_t)NMID * R_SZ * KTOT];
__device__ __nv_bfloat16 g_blo_mid[(size_t)NMID * R_SZ * KTOT];
__device__ __nv_bfloat16 g_bhi_last[(size_t)OUT_SZ * KTOT];
__device__ __nv_bfloat16 g_blo_last[(size_t)OUT_SZ * KTOT];

// ---------------------------------------------------------------------------
// PTX helpers (sm_80-era: cp.async, ldmatrix, mma.sync — NO tcgen05)
// ---------------------------------------------------------------------------
__device__ __forceinline__ uint32_t smem_u32(const void* p) {
    uint32_t a;
    asm("{ .reg .u64 t; cvta.to.shared.u64 t, %1; cvt.u32.u64 %0, t; }" : "=r"(a) : "l"(p));
    return a;
}
#define CP_ASYNC16(dst, src) \
    asm volatile("cp.async.cg.shared.global [%0], [%1], 16;" :: "r"(dst), "l"(src) : "memory")
#define CP_COMMIT() asm volatile("cp.async.commit_group;" ::: "memory")
#define CP_WAIT2()  asm volatile("cp.async.wait_group 2;" ::: "memory")

#define LDSM4(r0, r1, r2, r3, addr) \
    asm volatile("ldmatrix.sync.aligned.m8n8.x4.shared.b16 {%0,%1,%2,%3}, [%4];" \
                 : "=r"(r0), "=r"(r1), "=r"(r2), "=r"(r3) : "r"(addr))

#define MMA_BF16(d, a, b) \
    asm volatile("mma.sync.aligned.m16n8k16.row.col.f32.bf16.bf16.f32 " \
                 "{%0,%1,%2,%3}, {%4,%5,%6,%7}, {%8,%9}, {%0,%1,%2,%3};" \
                 : "+f"((d)[0]), "+f"((d)[1]), "+f"((d)[2]), "+f"((d)[3]) \
                 : "r"((a)[0]), "r"((a)[1]), "r"((a)[2]), "r"((a)[3]), \
                   "r"((b)[0]), "r"((b)[1]))

// 64B-row XOR swizzle: conflict-free across all 8-row ldmatrix phases.
__device__ __forceinline__ uint32_t sw64(uint32_t row, uint32_t c16) {
    return row * 64u + ((c16 ^ ((row >> 1) & 3u)) << 4);
}

// ---------------------------------------------------------------------------
// Precompute: tanh + bf16 hi/lo split + transpose
//   G [R, P, N] (n contiguous) -> hi/lo [N][j*512 + r] (k contiguous)
// ---------------------------------------------------------------------------
__global__ void split_transpose_kernel(const float* __restrict__ G,
                                       __nv_bfloat16* __restrict__ hi,
                                       __nv_bfloat16* __restrict__ lo,
                                       int N, size_t gStride, size_t oStride) {
    __shared__ float t[32][33];
    int layer = blockIdx.z / P_SZ;
    int j     = blockIdx.z % P_SZ;
    const float* Gp = G + (size_t)layer * gStride;
    __nv_bfloat16* hip = hi + (size_t)layer * oStride;
    __nv_bfloat16* lop = lo + (size_t)layer * oStride;
    int rt = blockIdx.x * 32, nt = blockIdx.y * 32;
    int tx = threadIdx.x, ty = threadIdx.y;   // block (32, 8)
#pragma unroll
    for (int yy = ty; yy < 32; yy += 8)
        t[yy][tx] = tanhf(Gp[((size_t)(rt + yy) * P_SZ + j) * N + nt + tx]);
    __syncthreads();
#pragma unroll
    for (int yy = ty; yy < 32; yy += 8) {
        int n = nt + yy, r = rt + tx;
        float x = t[tx][yy];
        __nv_bfloat16 h = __float2bfloat16_rn(x);
        size_t o = (size_t)n * KTOT + (size_t)j * R_SZ + r;
        hip[o] = h;
        lop[o] = __float2bfloat16_rn(x - __bfloat162float(h));
    }
}

__global__ void tanh_small_kernel(const float* __restrict__ src,
                                  float* __restrict__ dst, int n) {
    int i = blockIdx.x * blockDim.x + threadIdx.x;
    if (i < n) dst[i] = tanhf(src[i]);
}

// First core: res0[b,r] = sum_j tanh(G0)[j,r] * z[b,0]^j, hi/lo split output
__global__ void first_core_kernel(const float* __restrict__ z,
                                  __nv_bfloat16* __restrict__ rh,
                                  __nv_bfloat16* __restrict__ rl) {
    int b = blockIdx.x;
    int r = threadIdx.x;
    float zv = z[b * D_SZ + 0];
    float ph = 1.f, acc = 0.f;
#pragma unroll
    for (int j = 0; j < P_SZ; j++) {
        acc += g_tanh_g0[j * R_SZ + r] * ph;
        ph *= zv;
    }
    __nv_bfloat16 h = __float2bfloat16_rn(acc);
    rh[(size_t)b * R_SZ + r] = h;
    rl[(size_t)b * R_SZ + r] = __float2bfloat16_rn(acc - __bfloat162float(h));
}

// ---------------------------------------------------------------------------
// HMMA bf16 3-product-split GEMM with Horner phi folding.
// THREADS threads; warp grid (BM/WM) x (BN/WN). 4-stage cp.async pipeline.
// EPI 0: write bf16 hi/lo split (feeds next layer). EPI 1: write f32.
// ---------------------------------------------------------------------------
template<int BM, int BN, int WM, int WN, int THREADS, int EPI>
__global__ void __launch_bounds__(THREADS, 1)
tt_mma_kernel(const __nv_bfloat16* __restrict__ Ahi,
              const __nv_bfloat16* __restrict__ Alo,
              const __nv_bfloat16* __restrict__ Bhi,
              const __nv_bfloat16* __restrict__ Blo,
              const float* __restrict__ z, int zcol,
              float* __restrict__ outF,
              __nv_bfloat16* __restrict__ outH,
              __nv_bfloat16* __restrict__ outL, int Ntotal) {
    constexpr int MT = WM / 16, NT = WN / 8;
    constexpr int A_T = BM * 64;               // one A tile (hi or lo), bytes
    constexpr int B_T = BN * 64;
    constexpr int STAGE = 2 * A_T + 2 * B_T;
    constexpr int NSTAGE = 4;

    extern __shared__ __align__(16) char sm[];
    const uint32_t base = smem_u32(sm);

    const int tid = threadIdx.x, lane = tid & 31, wid = tid >> 5;
    const int m0 = blockIdx.y * BM, n0 = blockIdx.x * BN;
    constexpr int NWC = BN / WN;
    const int wm0 = (wid / NWC) * WM;
    const int wn0 = (wid % NWC) * WN;

    // per-lane z values for Horner scaling (rows r, r+8 per mt quad)
    float zA[MT], zB[MT];
#pragma unroll
    for (int mt = 0; mt < MT; mt++) {
        int rA = m0 + wm0 + mt * 16 + (lane >> 2);
        zA[mt] = z[(size_t)rA * D_SZ + zcol];
        zB[mt] = z[(size_t)(rA + 8) * D_SZ + zcol];
    }

    float acc[MT][NT][4];
#pragma unroll
    for (int mt = 0; mt < MT; mt++)
#pragma unroll
        for (int nt = 0; nt < NT; nt++)
#pragma unroll
            for (int q = 0; q < 4; q++) acc[mt][nt][q] = 0.f;

    auto produce = [&](int cc) {
        const int s = cc & (NSTAGE - 1);
        const int j = (P_SZ - 1) - cc / RCH;       // descending j
        const int rr = cc & (RCH - 1);
        const int roffA = rr * KC;
        const int koffB = j * R_SZ + rr * KC;
        const uint32_t aH = base + s * STAGE;
        const uint32_t aL = aH + A_T;
        const uint32_t bH = aH + 2 * A_T;
        const uint32_t bL = bH + B_T;
#pragma unroll
        for (int i = 0; i < (BM * 4) / THREADS; i++) {
            const int idx = tid + i * THREADS;
            const int row = idx >> 2, c16 = idx & 3;
            const uint32_t off = sw64(row, c16);
            const size_t go = (size_t)(m0 + row) * R_SZ + roffA + c16 * 8;
            CP_ASYNC16(aH + off, Ahi + go);
            CP_ASYNC16(aL + off, Alo + go);
        }
#pragma unroll
        for (int i = 0; i < (BN * 4) / THREADS; i++) {
            const int idx = tid + i * THREADS;
            const int row = idx >> 2, c16 = idx & 3;
            const uint32_t off = sw64(row, c16);
            const size_t go = (size_t)(n0 + row) * KTOT + koffB + c16 * 8;
            CP_ASYNC16(bH + off, Bhi + go);
            CP_ASYNC16(bL + off, Blo + go);
        }
        CP_COMMIT();
    };

    auto mma_chunk = [&](int s) {
        const uint32_t aH = base + s * STAGE;
        const uint32_t aL = aH + A_T;
        const uint32_t bH = aH + 2 * A_T;
        const uint32_t bL = bH + B_T;
#pragma unroll
        for (int ks = 0; ks < 2; ks++) {
            uint32_t bh[NT][2], bl[NT][2];
#pragma unroll
            for (int n2 = 0; n2 < NT / 2; n2++) {
                const uint32_t rowb = wn0 + n2 * 16 + ((lane >> 4) << 3) + (lane & 7);
                const uint32_t c16b = ((lane >> 3) & 1) + 2 * ks;
                LDSM4(bh[2 * n2][0], bh[2 * n2][1], bh[2 * n2 + 1][0], bh[2 * n2 + 1][1],
                      bH + sw64(rowb, c16b));
                LDSM4(bl[2 * n2][0], bl[2 * n2][1], bl[2 * n2 + 1][0], bl[2 * n2 + 1][1],
                      bL + sw64(rowb, c16b));
            }
            uint32_t a[MT][4];
#pragma unroll
            for (int mt = 0; mt < MT; mt++) {
                const uint32_t rowa = wm0 + mt * 16 + (lane & 15);
                LDSM4(a[mt][0], a[mt][1], a[mt][2], a[mt][3],
                      aH + sw64(rowa, (lane >> 4) + 2 * ks));
            }
#pragma unroll
            for (int mt = 0; mt < MT; mt++)
#pragma unroll
                for (int nt = 0; nt < NT; nt++) MMA_BF16(acc[mt][nt], a[mt], bh[nt]);
#pragma unroll
            for (int mt = 0; mt < MT; mt++)
#pragma unroll
                for (int nt = 0; nt < NT; nt++) MMA_BF16(acc[mt][nt], a[mt], bl[nt]);
#pragma unroll
            for (int mt = 0; mt < MT; mt++) {
                const uint32_t rowa = wm0 + mt * 16 + (lane & 15);
                LDSM4(a[mt][0], a[mt][1], a[mt][2], a[mt][3],
                      aL + sw64(rowa, (lane >> 4) + 2 * ks));
            }
#pragma unroll
            for (int mt = 0; mt < MT; mt++)
#pragma unroll
                for (int nt = 0; nt < NT; nt++) MMA_BF16(acc[mt][nt], a[mt], bh[nt]);
        }
    };

    // prologue: 3 stages in flight
    produce(0); produce(1); produce(2);

    for (int c = 0; c < NCH; c++) {
        CP_WAIT2();
        __syncthreads();
        if (c + 3 < NCH) produce(c + 3); else CP_COMMIT();
        if (c && (c & (RCH - 1)) == 0) {
            // Horner: entering next-lower j — scale accumulators by z
#pragma unroll
            for (int mt = 0; mt < MT; mt++)
#pragma unroll
                for (int nt = 0; nt < NT; nt++) {
                    acc[mt][nt][0] *= zA[mt]; acc[mt][nt][1] *= zA[mt];
                    acc[mt][nt][2] *= zB[mt]; acc[mt][nt][3] *= zB[mt];
                }
        }
        mma_chunk(c & (NSTAGE - 1));
    }

    // epilogue
#pragma unroll
    for (int mt = 0; mt < MT; mt++) {
        const int row0 = m0 + wm0 + mt * 16 + (lane >> 2);
#pragma unroll
        for (int nt = 0; nt < NT; nt++) {
            const int col = n0 + wn0 + nt * 8 + (lane & 3) * 2;
            if (EPI == 1) {
                *reinterpret_cast<float2*>(&outF[(size_t)row0 * Ntotal + col]) =
                    make_float2(acc[mt][nt][0], acc[mt][nt][1]);
                *reinterpret_cast<float2*>(&outF[(size_t)(row0 + 8) * Ntotal + col]) =
                    make_float2(acc[mt][nt][2], acc[mt][nt][3]);
            } else {
#pragma unroll
                for (int h = 0; h < 2; h++) {
                    const int row = row0 + 8 * h;
                    float v0 = acc[mt][nt][2 * h], v1 = acc[mt][nt][2 * h + 1];
                    __nv_bfloat16 h0 = __float2bfloat16_rn(v0);
                    __nv_bfloat16 h1 = __float2bfloat16_rn(v1);
                    __nv_bfloat162 hv; hv.x = h0; hv.y = h1;
                    __nv_bfloat162 lv;
                    lv.x = __float2bfloat16_rn(v0 - __bfloat162float(h0));
                    lv.y = __float2bfloat16_rn(v1 - __bfloat162float(h1));
                    *reinterpret_cast<__nv_bfloat162*>(&outH[(size_t)row * R_SZ + col]) = hv;
                    *reinterpret_cast<__nv_bfloat162*>(&outL[(size_t)row * R_SZ + col]) = lv;
                }
            }
        }
    }
}

// ---------------------------------------------------------------------------
// Launch (graph-capturable, allocation-free)
// Inputs: z [B,D] f32, G0 [P,R] f32, G_mid [6,R,P,R] f32, G_last [R,P,OUT] f32, t
// Output: [B, OUT] f32
// ---------------------------------------------------------------------------
extern "C" void kernel_launch(void* const* d_in, const int* in_sizes, int n_in,
                              void* d_out, int out_size) {
    (void)in_sizes; (void)n_in; (void)out_size;
    const float* z     = (const float*)d_in[0];
    const float* G0    = (const float*)d_in[1];
    const float* Gmid  = (const float*)d_in[2];
    const float* Glast = (const float*)d_in[3];
    float* out = (float*)d_out;

    float* p_tg0;
    __nv_bfloat16 *p_rh0, *p_rl0, *p_rh1, *p_rl1, *p_bhi, *p_blo, *p_bhiL, *p_bloL;
    cudaGetSymbolAddress((void**)&p_tg0,  g_tanh_g0);
    cudaGetSymbolAddress((void**)&p_rh0,  g_rh0);
    cudaGetSymbolAddress((void**)&p_rl0,  g_rl0);
    cudaGetSymbolAddress((void**)&p_rh1,  g_rh1);
    cudaGetSymbolAddress((void**)&p_rl1,  g_rl1);
    cudaGetSymbolAddress((void**)&p_bhi,  g_bhi_mid);
    cudaGetSymbolAddress((void**)&p_blo,  g_blo_mid);
    cudaGetSymbolAddress((void**)&p_bhiL, g_bhi_last);
    cudaGetSymbolAddress((void**)&p_bloL, g_blo_last);

    // dynamic smem: 4 stages x (2*BM + 2*BN) * 64 bytes
    const int SMEM_MID  = 4 * (2 * 256 + 2 * 128) * 64;  // 196608
    const int SMEM_LAST = 4 * (2 * 64 + 2 * 64) * 64;    // 65536
    cudaFuncSetAttribute((const void*)tt_mma_kernel<256, 128, 64, 32, 512, 0>,
                         cudaFuncAttributeMaxDynamicSharedMemorySize, SMEM_MID);
    cudaFuncSetAttribute((const void*)tt_mma_kernel<64, 64, 32, 16, 256, 1>,
                         cudaFuncAttributeMaxDynamicSharedMemorySize, SMEM_LAST);

    // precompute
    tanh_small_kernel<<<(P_SZ * R_SZ + 255) / 256, 256>>>(G0, p_tg0, P_SZ * R_SZ);
    split_transpose_kernel<<<dim3(R_SZ / 32, R_SZ / 32, NMID * P_SZ), dim3(32, 8)>>>(
        Gmid, p_bhi, p_blo, R_SZ,
        (size_t)R_SZ * P_SZ * R_SZ, (size_t)R_SZ * KTOT);
    split_transpose_kernel<<<dim3(R_SZ / 32, OUT_SZ / 32, P_SZ), dim3(32, 8)>>>(
        Glast, p_bhiL, p_bloL, OUT_SZ, 0, 0);

    // first core -> split res0
    first_core_kernel<<<B_SZ, R_SZ>>>(z, p_rh0, p_rl0);

    // six middle cores (ping-pong on split res) — 512 threads, warp grid 4x4
    __nv_bfloat16 *ch = p_rh0, *cl = p_rl0, *nh = p_rh1, *nl = p_rl1;
    for (int i = 0; i < NMID; i++) {
        tt_mma_kernel<256, 128, 64, 32, 512, 0>
            <<<dim3(R_SZ / 128, B_SZ / 256), 512, SMEM_MID>>>(
            ch, cl,
            p_bhi + (size_t)i * R_SZ * KTOT, p_blo + (size_t)i * R_SZ * KTOT,
            z, i + 1, nullptr, nh, nl, R_SZ);
        __nv_bfloat16* t;
        t = ch; ch = nh; nh = t;
        t = cl; cl = nl; nl = t;
    }

    // last core -> d_out [B, OUT] f32
    tt_mma_kernel<64, 64, 32, 16, 256, 1><<<dim3(1, B_SZ / 64), 256, SMEM_LAST>>>(
        ch, cl, p_bhiL, p_bloL, z, D_SZ - 1, out, nullptr, nullptr, OUT_SZ);
}